// round 3
// baseline (speedup 1.0000x reference)
#include <cuda_runtime.h>
#include <math.h>

#define TT 5
#define ZZ 32
#define YY 512
#define XX 512
#define N_RAYS 10000
#define N_STEPS 768
#define VOXEL 0.2f
#define L_STEPS 8                       // steps per lane
#define ROUND_STEPS (32 * L_STEPS)      // 256 steps per warp-round
#define N_ROUNDS (N_STEPS / ROUND_STEPS)

__global__ void zero_out_kernel(float* __restrict__ out)
{
    out[0] = 0.0f;
    out[1] = 0.0f;
    out[2] = 0.0f;
}

__global__ void __launch_bounds__(128)
ray_march_loss_kernel(const float* __restrict__ grid,
                      const float* __restrict__ origin,   // [T,3]
                      const float* __restrict__ points,   // [N_RAYS,3]
                      const int*   __restrict__ tindex,   // [N_RAYS]
                      float* __restrict__ out)            // [3]
{
    const unsigned FULL = 0xffffffffu;
    int gwarp = (blockIdx.x * blockDim.x + threadIdx.x) >> 5;
    int lane  = threadIdx.x & 31;
    int wid   = threadIdx.x >> 5;   // warp in block (0..3)

    __shared__ float s1[4], s2[4], s3[4];

    float l1 = 0.0f, l2 = 0.0f, l3 = 0.0f;

    if (gwarp < N_RAYS) {
        const float offx = -51.2f, offy = -51.2f, offz = -3.2f;
        const float inv_vox = 5.0f;  // 1/0.2

        int ti = tindex[gwarp];

        float ox = (origin[ti * 3 + 0] - offx) * inv_vox;
        float oy = (origin[ti * 3 + 1] - offy) * inv_vox;
        float oz = (origin[ti * 3 + 2] - offz) * inv_vox;

        float px = (points[gwarp * 3 + 0] - offx) * inv_vox;
        float py = (points[gwarp * 3 + 1] - offy) * inv_vox;
        float pz = (points[gwarp * 3 + 2] - offz) * inv_vox;

        float dx = px - ox, dy = py - oy, dz = pz - oz;
        float gt = sqrtf(dx * dx + dy * dy + dz * dz);
        float rinv = 1.0f / fmaxf(gt, 1e-6f);
        float ux = dx * rinv, uy = dy * rinv, uz = dz * rinv;

        // ---- Slab clipping (conservative; per-step inb guard keeps exactness)
        float tmin = 0.0f, tmax = (float)N_STEPS;
        bool empty = false;
        {
            float o[3] = {ox, oy, oz};
            float u[3] = {ux, uy, uz};
            float dim[3] = {(float)XX, (float)YY, (float)ZZ};
            #pragma unroll
            for (int a = 0; a < 3; ++a) {
                if (fabsf(u[a]) > 1e-8f) {
                    float inv = 1.0f / u[a];
                    float t0 = (0.0f   - o[a]) * inv;
                    float t1 = (dim[a] - o[a]) * inv;
                    tmin = fmaxf(tmin, fminf(t0, t1));
                    tmax = fminf(tmax, fmaxf(t0, t1));
                } else if (o[a] < 0.0f || o[a] >= dim[a]) {
                    empty = true;
                }
            }
        }

        float pred = 0.0f;

        if (!empty && tmax > tmin) {
            int k_lo = max(0, (int)floorf(tmin - 0.5f) - 1);
            int k_hi = min(N_STEPS - 1, (int)ceilf(tmax - 0.5f) + 1);
            int r0 = k_lo / ROUND_STEPS;
            int r1 = k_hi / ROUND_STEPS;

            const float* base = grid + ((size_t)ti << 23);  // ti * 32*512*512

            float S = 0.0f;

            #pragma unroll 1
            for (int r = r0; r <= r1; ++r) {
                // Lane handles steps [r*256 + lane*8, +8)
                float tbase = (float)(r * ROUND_STEPS + lane * L_STEPS) + 0.5f;
                float fx0 = ox + ux * tbase;
                float fy0 = oy + uy * tbase;
                float fz0 = oz + uz * tbase;

                float tau[L_STEPS];
                #pragma unroll
                for (int j = 0; j < L_STEPS; ++j) {
                    float xx = fx0 + (float)j * ux;
                    float yy = fy0 + (float)j * uy;
                    float zz = fz0 + (float)j * uz;
                    int ix = __float2int_rd(xx);
                    int iy = __float2int_rd(yy);
                    int iz = __float2int_rd(zz);
                    bool inb = ((unsigned)ix < XX) & ((unsigned)iy < YY) &
                               ((unsigned)iz < ZZ);
                    float s = 0.0f;
                    if (inb)
                        s = __ldg(base + (((iz << 9) + iy) << 9) + ix);
                    tau[j] = fmaxf(s, 0.0f);
                }

                float lsum = 0.0f;
                #pragma unroll
                for (int j = 0; j < L_STEPS; ++j) lsum += tau[j];

                // Single warp scan over lane sums
                float scan = lsum;
                #pragma unroll
                for (int o = 1; o < 32; o <<= 1) {
                    float v = __shfl_up_sync(FULL, scan, o);
                    if (lane >= o) scan += v;
                }
                float excl = scan - lsum;
                float Stot = __shfl_sync(FULL, scan, 31);

                // Attenuation factors (independent MUFU ops)
                float A[L_STEPS];
                #pragma unroll
                for (int j = 0; j < L_STEPS; ++j) A[j] = __expf(-tau[j]);

                float E = __expf(-(S + excl));
                #pragma unroll
                for (int j = 0; j < L_STEPS; ++j) {
                    pred += E * (1.0f - A[j]) * (tbase + (float)j);
                    E *= A[j];
                }

                S += Stot;
                if (S > 25.0f) break;   // remaining transmittance < 1.4e-11
            }

            // Warp reduction of pred
            #pragma unroll
            for (int o = 16; o > 0; o >>= 1)
                pred += __shfl_xor_sync(FULL, pred, o);
        }

        if (lane == 0) {
            float p = pred * VOXEL;
            float g = gt * VOXEL;
            float d = g - p;
            float ad = fabsf(d);
            l1 = ad;
            l2 = 0.5f * d * d;
            l3 = ad / fmaxf(g, 1e-6f);
        }
    }

    if (lane == 0) {
        s1[wid] = l1; s2[wid] = l2; s3[wid] = l3;
    }
    __syncthreads();
    if (wid == 0 && lane == 0) {
        float a = 0.0f, b = 0.0f, cc = 0.0f;
        #pragma unroll
        for (int i = 0; i < 4; ++i) { a += s1[i]; b += s2[i]; cc += s3[i]; }
        const float inv_count = 1.0f / (float)N_RAYS;
        atomicAdd(&out[0], a  * inv_count);
        atomicAdd(&out[1], b  * inv_count);
        atomicAdd(&out[2], cc * inv_count);
    }
}

extern "C" void kernel_launch(void* const* d_in, const int* in_sizes, int n_in,
                              void* d_out, int out_size)
{
    const float* grid    = (const float*)d_in[0];  // [1,5,32,512,512]
    const float* origin  = (const float*)d_in[1];  // [1,5,3]
    const float* points  = (const float*)d_in[2];  // [1,10000,3]
    const int*   tindex  = (const int*)d_in[3];    // [1,10000]
    float* out = (float*)d_out;

    zero_out_kernel<<<1, 1>>>(out);

    int threads = 128;  // 4 warps = 4 rays per block
    int blocks = (N_RAYS * 32 + threads - 1) / threads;
    ray_march_loss_kernel<<<blocks, threads>>>(grid, origin, points, tindex, out);
}

// round 4
// speedup vs baseline: 1.0944x; 1.0944x over previous
#include <cuda_runtime.h>
#include <math.h>

#define TT 5
#define ZZ 32
#define YY 512
#define XX 512
#define N_RAYS 10000
#define N_STEPS 768
#define VOXEL 0.2f
#define PAIR_STEPS 64
#define N_PAIRS (N_STEPS / PAIR_STEPS)   // 12

__global__ void zero_out_kernel(float* __restrict__ out)
{
    out[0] = 0.0f;
    out[1] = 0.0f;
    out[2] = 0.0f;
}

__device__ __forceinline__ float fetch_tau(const float* __restrict__ base,
                                           float ox, float oy, float oz,
                                           float ux, float uy, float uz,
                                           int k)   // absolute step index
{
    float t = (float)k + 0.5f;
    float fx = ox + ux * t;
    float fy = oy + uy * t;
    float fz = oz + uz * t;
    int ix = __float2int_rd(fx);
    int iy = __float2int_rd(fy);
    int iz = __float2int_rd(fz);
    bool inb = ((unsigned)ix < XX) & ((unsigned)iy < YY) & ((unsigned)iz < ZZ);
    float s = 0.0f;
    if (inb)
        s = __ldg(base + (((iz << 9) + iy) << 9) + ix);
    return fmaxf(s, 0.0f);
}

__global__ void __launch_bounds__(128)
ray_march_loss_kernel(const float* __restrict__ grid,
                      const float* __restrict__ origin,   // [T,3]
                      const float* __restrict__ points,   // [N_RAYS,3]
                      const int*   __restrict__ tindex,   // [N_RAYS]
                      float* __restrict__ out)            // [3]
{
    const unsigned FULL = 0xffffffffu;
    int gwarp = (blockIdx.x * blockDim.x + threadIdx.x) >> 5;
    int lane  = threadIdx.x & 31;
    int wid   = threadIdx.x >> 5;   // warp in block (0..3)

    __shared__ float s1[4], s2[4], s3[4];

    float l1 = 0.0f, l2 = 0.0f, l3 = 0.0f;

    if (gwarp < N_RAYS) {
        const float offx = -51.2f, offy = -51.2f, offz = -3.2f;
        const float inv_vox = 5.0f;  // 1/0.2

        int ti = tindex[gwarp];

        float ox = (origin[ti * 3 + 0] - offx) * inv_vox;
        float oy = (origin[ti * 3 + 1] - offy) * inv_vox;
        float oz = (origin[ti * 3 + 2] - offz) * inv_vox;

        float px = (points[gwarp * 3 + 0] - offx) * inv_vox;
        float py = (points[gwarp * 3 + 1] - offy) * inv_vox;
        float pz = (points[gwarp * 3 + 2] - offz) * inv_vox;

        float dx = px - ox, dy = py - oy, dz = pz - oz;
        float gt = sqrtf(dx * dx + dy * dy + dz * dz);
        float rinv = 1.0f / fmaxf(gt, 1e-6f);
        float ux = dx * rinv, uy = dy * rinv, uz = dz * rinv;

        // ---- Slab clipping (conservative; per-step inb guard keeps exactness)
        float tmin = 0.0f, tmax = (float)N_STEPS;
        bool empty = false;
        {
            float o[3] = {ox, oy, oz};
            float u[3] = {ux, uy, uz};
            float dim[3] = {(float)XX, (float)YY, (float)ZZ};
            #pragma unroll
            for (int a = 0; a < 3; ++a) {
                if (fabsf(u[a]) > 1e-8f) {
                    float inv = 1.0f / u[a];
                    float t0 = (0.0f   - o[a]) * inv;
                    float t1 = (dim[a] - o[a]) * inv;
                    tmin = fmaxf(tmin, fminf(t0, t1));
                    tmax = fminf(tmax, fmaxf(t0, t1));
                } else if (o[a] < 0.0f || o[a] >= dim[a]) {
                    empty = true;
                }
            }
        }

        float pred = 0.0f;

        if (!empty && tmax > tmin) {
            int k_lo = max(0, (int)floorf(tmin - 0.5f) - 1);
            int k_hi = min(N_STEPS - 1, (int)ceilf(tmax - 0.5f) + 1);
            int p0 = k_lo / PAIR_STEPS;
            int p1 = k_hi / PAIR_STEPS;

            const float* base = grid + ((size_t)ti << 23);  // ti * 32*512*512

            float S = 0.0f;

            // Prefetch first pair
            int kb0 = p0 * PAIR_STEPS;
            float ta = fetch_tau(base, ox, oy, oz, ux, uy, uz, kb0 + lane);
            float tb = fetch_tau(base, ox, oy, oz, ux, uy, uz, kb0 + 32 + lane);

            #pragma unroll 1
            for (int p = p0; p <= p1; ++p) {
                int kb = p * PAIR_STEPS;

                float na = 0.0f, nb = 0.0f;
                if (p < p1) {
                    na = fetch_tau(base, ox, oy, oz, ux, uy, uz, kb + PAIR_STEPS + lane);
                    nb = fetch_tau(base, ox, oy, oz, ux, uy, uz, kb + PAIR_STEPS + 32 + lane);
                }

                // Two independent warp scans (pipelined SHFL chains)
                float sa = ta, sb = tb;
                #pragma unroll
                for (int o = 1; o < 32; o <<= 1) {
                    float va = __shfl_up_sync(FULL, sa, o);
                    float vb = __shfl_up_sync(FULL, sb, o);
                    if (lane >= o) { sa += va; sb += vb; }
                }
                float totA = __shfl_sync(FULL, sa, 31);
                float totB = __shfl_sync(FULL, sb, 31);

                float exclA = S + (sa - ta);
                float exclB = S + totA + (sb - tb);

                float Ea = __expf(-exclA);
                float Eb = __expf(-exclB);
                float Aa = __expf(-ta);
                float Ab = __expf(-tb);

                float t_a = (float)(kb + lane) + 0.5f;
                float t_b = t_a + 32.0f;

                pred += Ea * (1.0f - Aa) * t_a;
                pred += Eb * (1.0f - Ab) * t_b;

                S += totA + totB;
                ta = na; tb = nb;
                if (S > 25.0f) break;   // remaining transmittance < 1.4e-11
            }

            // Warp reduction of pred
            #pragma unroll
            for (int o = 16; o > 0; o >>= 1)
                pred += __shfl_xor_sync(FULL, pred, o);
        }

        if (lane == 0) {
            float p = pred * VOXEL;
            float g = gt * VOXEL;
            float d = g - p;
            float ad = fabsf(d);
            l1 = ad;
            l2 = 0.5f * d * d;
            l3 = ad / fmaxf(g, 1e-6f);
        }
    }

    if (lane == 0) {
        s1[wid] = l1; s2[wid] = l2; s3[wid] = l3;
    }
    __syncthreads();
    if (wid == 0 && lane == 0) {
        float a = 0.0f, b = 0.0f, cc = 0.0f;
        #pragma unroll
        for (int i = 0; i < 4; ++i) { a += s1[i]; b += s2[i]; cc += s3[i]; }
        const float inv_count = 1.0f / (float)N_RAYS;
        atomicAdd(&out[0], a  * inv_count);
        atomicAdd(&out[1], b  * inv_count);
        atomicAdd(&out[2], cc * inv_count);
    }
}

extern "C" void kernel_launch(void* const* d_in, const int* in_sizes, int n_in,
                              void* d_out, int out_size)
{
    const float* grid    = (const float*)d_in[0];  // [1,5,32,512,512]
    const float* origin  = (const float*)d_in[1];  // [1,5,3]
    const float* points  = (const float*)d_in[2];  // [1,10000,3]
    const int*   tindex  = (const int*)d_in[3];    // [1,10000]
    float* out = (float*)d_out;

    zero_out_kernel<<<1, 1>>>(out);

    int threads = 128;  // 4 warps = 4 rays per block
    int blocks = (N_RAYS * 32 + threads - 1) / threads;
    ray_march_loss_kernel<<<blocks, threads>>>(grid, origin, points, tindex, out);
}

// round 5
// speedup vs baseline: 1.5429x; 1.4099x over previous
#include <cuda_runtime.h>
#include <math.h>

#define TT 5
#define ZZ 32
#define YY 512
#define XX 512
#define N_RAYS 10000
#define N_STEPS 768
#define VOXEL 0.2f
#define N_CHUNKS (N_STEPS / 32)

__global__ void zero_out_kernel(float* __restrict__ out)
{
    out[0] = 0.0f;
    out[1] = 0.0f;
    out[2] = 0.0f;
}

__device__ __forceinline__ float fetch_tau(const float* __restrict__ base,
                                           float ox, float oy, float oz,
                                           float ux, float uy, float uz,
                                           int k)   // absolute step index
{
    float t = (float)k + 0.5f;
    float fx = ox + ux * t;
    float fy = oy + uy * t;
    float fz = oz + uz * t;
    int ix = __float2int_rd(fx);
    int iy = __float2int_rd(fy);
    int iz = __float2int_rd(fz);
    bool inb = ((unsigned)ix < XX) & ((unsigned)iy < YY) & ((unsigned)iz < ZZ);
    float s = 0.0f;
    if (inb)
        s = __ldg(base + (((iz << 9) + iy) << 9) + ix);
    return fmaxf(s, 0.0f);
}

__global__ void __launch_bounds__(256)
ray_march_loss_kernel(const float* __restrict__ grid,
                      const float* __restrict__ origin,   // [T,3]
                      const float* __restrict__ points,   // [N_RAYS,3]
                      const int*   __restrict__ tindex,   // [N_RAYS]
                      float* __restrict__ out)            // [3]
{
    const unsigned FULL = 0xffffffffu;
    int gwarp = (blockIdx.x * blockDim.x + threadIdx.x) >> 5;
    int lane  = threadIdx.x & 31;
    int wid   = threadIdx.x >> 5;   // warp in block (0..7)

    __shared__ float s1[8], s2[8], s3[8];

    float l1 = 0.0f, l2 = 0.0f, l3 = 0.0f;

    if (gwarp < N_RAYS) {
        const float offx = -51.2f, offy = -51.2f, offz = -3.2f;
        const float inv_vox = 5.0f;  // 1/0.2

        int ti = tindex[gwarp];

        float ox = (origin[ti * 3 + 0] - offx) * inv_vox;
        float oy = (origin[ti * 3 + 1] - offy) * inv_vox;
        float oz = (origin[ti * 3 + 2] - offz) * inv_vox;

        float px = (points[gwarp * 3 + 0] - offx) * inv_vox;
        float py = (points[gwarp * 3 + 1] - offy) * inv_vox;
        float pz = (points[gwarp * 3 + 2] - offz) * inv_vox;

        float dx = px - ox, dy = py - oy, dz = pz - oz;
        float gt = sqrtf(dx * dx + dy * dy + dz * dz);
        float rinv = 1.0f / fmaxf(gt, 1e-6f);
        float ux = dx * rinv, uy = dy * rinv, uz = dz * rinv;

        // ---- Slab clipping (conservative; per-step inb guard keeps exactness)
        float tmin = 0.0f, tmax = (float)N_STEPS;
        bool empty = false;
        {
            float o[3] = {ox, oy, oz};
            float u[3] = {ux, uy, uz};
            float dim[3] = {(float)XX, (float)YY, (float)ZZ};
            #pragma unroll
            for (int a = 0; a < 3; ++a) {
                if (fabsf(u[a]) > 1e-8f) {
                    float inv = 1.0f / u[a];
                    float t0 = (0.0f   - o[a]) * inv;
                    float t1 = (dim[a] - o[a]) * inv;
                    tmin = fmaxf(tmin, fminf(t0, t1));
                    tmax = fminf(tmax, fmaxf(t0, t1));
                } else if (o[a] < 0.0f || o[a] >= dim[a]) {
                    empty = true;
                }
            }
        }

        float pred = 0.0f;

        if (!empty && tmax > tmin) {
            int k_lo = max(0, (int)floorf(tmin - 0.5f) - 1);
            int k_hi = min(N_STEPS - 1, (int)ceilf(tmax - 0.5f) + 1);
            int c0 = k_lo >> 5;
            int c1 = k_hi >> 5;

            const float* base = grid + ((size_t)ti << 23);  // ti * 32*512*512

            float S = 0.0f;

            // Software pipeline, depth 2
            float t_cur = fetch_tau(base, ox, oy, oz, ux, uy, uz, (c0 << 5) + lane);
            float t_n1  = (c0 + 1 <= c1)
                        ? fetch_tau(base, ox, oy, oz, ux, uy, uz, ((c0 + 1) << 5) + lane)
                        : 0.0f;

            #pragma unroll 1
            for (int c = c0; c <= c1; ++c) {
                float t_n2 = 0.0f;
                if (c + 2 <= c1)
                    t_n2 = fetch_tau(base, ox, oy, oz, ux, uy, uz, ((c + 2) << 5) + lane);

                // Warp inclusive scan of t_cur
                float scan = t_cur;
                #pragma unroll
                for (int o = 1; o < 32; o <<= 1) {
                    float v = __shfl_up_sync(FULL, scan, o);
                    if (lane >= o) scan += v;
                }
                float tot = __shfl_sync(FULL, scan, 31);

                // w*t = (exp(-(S+excl)) - exp(-(S+incl))) * t   (independent MUFUs)
                float excl = S + (scan - t_cur);
                float incl = S + scan;
                float t = (float)((c << 5) + lane) + 0.5f;
                pred += (__expf(-excl) - __expf(-incl)) * t;

                S += tot;
                t_cur = t_n1;
                t_n1  = t_n2;
                if (S > 25.0f) break;   // remaining transmittance < 1.4e-11
            }

            // Warp reduction of pred
            #pragma unroll
            for (int o = 16; o > 0; o >>= 1)
                pred += __shfl_xor_sync(FULL, pred, o);
        }

        if (lane == 0) {
            float p = pred * VOXEL;
            float g = gt * VOXEL;
            float d = g - p;
            float ad = fabsf(d);
            l1 = ad;
            l2 = 0.5f * d * d;
            l3 = ad / fmaxf(g, 1e-6f);
        }
    }

    if (lane == 0) {
        s1[wid] = l1; s2[wid] = l2; s3[wid] = l3;
    }
    __syncthreads();
    if (wid == 0 && lane == 0) {
        float a = 0.0f, b = 0.0f, cc = 0.0f;
        #pragma unroll
        for (int i = 0; i < 8; ++i) { a += s1[i]; b += s2[i]; cc += s3[i]; }
        const float inv_count = 1.0f / (float)N_RAYS;
        atomicAdd(&out[0], a  * inv_count);
        atomicAdd(&out[1], b  * inv_count);
        atomicAdd(&out[2], cc * inv_count);
    }
}

extern "C" void kernel_launch(void* const* d_in, const int* in_sizes, int n_in,
                              void* d_out, int out_size)
{
    const float* grid    = (const float*)d_in[0];  // [1,5,32,512,512]
    const float* origin  = (const float*)d_in[1];  // [1,5,3]
    const float* points  = (const float*)d_in[2];  // [1,10000,3]
    const int*   tindex  = (const int*)d_in[3];    // [1,10000]
    float* out = (float*)d_out;

    zero_out_kernel<<<1, 1>>>(out);

    int threads = 256;  // 8 warps = 8 rays per block
    int blocks = (N_RAYS * 32 + threads - 1) / threads;
    ray_march_loss_kernel<<<blocks, threads>>>(grid, origin, points, tindex, out);
}